// round 6
// baseline (speedup 1.0000x reference)
#include <cuda_runtime.h>

// Problem constants (fixed by the reference).
#define B_SZ   32
#define N_IN   1024
#define N_OUT  1024
#define BB     4                   // batches per CTA (W register reuse factor)
#define NB     (B_SZ / BB)         // 8 batch groups
#define NCHUNK 64                  // i-dimension split
#define CHUNK  (N_IN / NCHUNK)     // 16 i-rows per block
#define THREADS 256                // each thread: 4 contiguous o-columns (float4)
#define STRIDE (N_OUT / 4)         // 256 float4 per i-row

__global__ void zero_out_kernel(float* __restrict__ out, int n) {
    int idx = blockIdx.x * blockDim.x + threadIdx.x;
    if (idx < n) out[idx] = 0.0f;
}

__global__ __launch_bounds__(THREADS, 2)
void synapses_kernel(const float* __restrict__ in_spikes,  // [B, N_IN]
                     const float* __restrict__ mem,        // [B, N_OUT]
                     const float* __restrict__ rev,        // [B, N_IN]
                     const float* __restrict__ syn,        // [B, N_IN, N_OUT]
                     const float* __restrict__ weights,    // [N_IN, N_OUT]
                     float* __restrict__ out)              // [B, N_OUT]
{
    __shared__ float s_sp[BB][CHUNK];
    __shared__ float s_rv[BB][CHUNK];

    const int b0 = blockIdx.y * BB;
    const int i0 = blockIdx.x * CHUNK;
    const int t  = threadIdx.x;

    // Stage per-(batch,i) scalars for this chunk.
    if (t < BB * CHUNK) {
        const int bb = t / CHUNK;
        const int ii = t % CHUNK;
        s_sp[bb][ii] = in_spikes[(b0 + bb) * N_IN + i0 + ii];
        s_rv[bb][ii] = rev[(b0 + bb) * N_IN + i0 + ii];
    }
    __syncthreads();

    const float decay = 1.0f - 1.0f / 5.0f;  // TAU = 5

    const float4* __restrict__ w4 =
        (const float4*)(weights + (size_t)i0 * N_OUT);

    const float4* sb[BB];
    #pragma unroll
    for (int bb = 0; bb < BB; ++bb)
        sb[bb] = (const float4*)(syn + ((size_t)(b0 + bb) * N_IN + i0) * N_OUT);

    float4 ar[BB], as[BB];
    #pragma unroll
    for (int bb = 0; bb < BB; ++bb) {
        ar[bb] = make_float4(0.f, 0.f, 0.f, 0.f);  // Σ cond*rev
        as[bb] = make_float4(0.f, 0.f, 0.f, 0.f);  // Σ cond
    }

    // 2 i-rows per iteration, W loaded ONCE and applied to 4 batches.
    // All 10 float4 loads front-batched -> MLP_eff ~10 per thread.
    for (int i = 0; i < CHUNK; i += 2) {
        const float4 w0 = __ldg(w4 + (i + 0) * STRIDE + t);
        const float4 w1 = __ldg(w4 + (i + 1) * STRIDE + t);

        float4 s0[BB], s1[BB];
        #pragma unroll
        for (int bb = 0; bb < BB; ++bb) {
            s0[bb] = __ldcs(sb[bb] + (i + 0) * STRIDE + t);  // streaming
            s1[bb] = __ldcs(sb[bb] + (i + 1) * STRIDE + t);
        }

        #pragma unroll
        for (int bb = 0; bb < BB; ++bb) {
            {
                const float sp = s_sp[bb][i + 0], rv = s_rv[bb][i + 0];
                float c0 = fmaf(s0[bb].x, decay, sp) * w0.x;
                float c1 = fmaf(s0[bb].y, decay, sp) * w0.y;
                float c2 = fmaf(s0[bb].z, decay, sp) * w0.z;
                float c3 = fmaf(s0[bb].w, decay, sp) * w0.w;
                ar[bb].x = fmaf(c0, rv, ar[bb].x);  as[bb].x += c0;
                ar[bb].y = fmaf(c1, rv, ar[bb].y);  as[bb].y += c1;
                ar[bb].z = fmaf(c2, rv, ar[bb].z);  as[bb].z += c2;
                ar[bb].w = fmaf(c3, rv, ar[bb].w);  as[bb].w += c3;
            }
            {
                const float sp = s_sp[bb][i + 1], rv = s_rv[bb][i + 1];
                float c0 = fmaf(s1[bb].x, decay, sp) * w1.x;
                float c1 = fmaf(s1[bb].y, decay, sp) * w1.y;
                float c2 = fmaf(s1[bb].z, decay, sp) * w1.z;
                float c3 = fmaf(s1[bb].w, decay, sp) * w1.w;
                ar[bb].x = fmaf(c0, rv, ar[bb].x);  as[bb].x += c0;
                ar[bb].y = fmaf(c1, rv, ar[bb].y);  as[bb].y += c1;
                ar[bb].z = fmaf(c2, rv, ar[bb].z);  as[bb].z += c2;
                ar[bb].w = fmaf(c3, rv, ar[bb].w);  as[bb].w += c3;
            }
        }
    }

    // Partial contribution of this i-chunk (linear in the i-partition).
    const int o = t * 4;
    #pragma unroll
    for (int bb = 0; bb < BB; ++bb) {
        const float4 m = *(const float4*)(mem + (size_t)(b0 + bb) * N_OUT + o);
        float* dst = out + (size_t)(b0 + bb) * N_OUT + o;
        atomicAdd(dst + 0, fmaf(-m.x, as[bb].x, ar[bb].x));
        atomicAdd(dst + 1, fmaf(-m.y, as[bb].y, ar[bb].y));
        atomicAdd(dst + 2, fmaf(-m.z, as[bb].z, ar[bb].z));
        atomicAdd(dst + 3, fmaf(-m.w, as[bb].w, ar[bb].w));
    }
}

extern "C" void kernel_launch(void* const* d_in, const int* in_sizes, int n_in,
                              void* d_out, int out_size) {
    const float* in_spikes = (const float*)d_in[0];
    const float* mem       = (const float*)d_in[1];
    const float* rev       = (const float*)d_in[2];
    const float* syn       = (const float*)d_in[3];
    const float* weights   = (const float*)d_in[4];
    float* out = (float*)d_out;

    zero_out_kernel<<<(B_SZ * N_OUT + 255) / 256, 256>>>(out, B_SZ * N_OUT);

    dim3 grid(NCHUNK, NB);  // 64 x 8 = 512 CTAs
    synapses_kernel<<<grid, THREADS>>>(in_spikes, mem, rev, syn, weights, out);
}

// round 9
// speedup vs baseline: 1.1344x; 1.1344x over previous
#include <cuda_runtime.h>

// Problem constants (fixed by the reference).
#define B_SZ   32
#define N_IN   1024
#define N_OUT  1024
#define BB     2                   // batches per CTA (W register reuse factor)
#define NB     (B_SZ / BB)         // 16 batch groups
#define NCHUNK 32                  // i-dimension split
#define CHUNK  (N_IN / NCHUNK)     // 32 i-rows per block
#define THREADS 256                // each thread: 4 contiguous o-columns (float4)
#define STRIDE (N_OUT / 4)         // 256 float4 per i-row

__global__ void zero_out_kernel(float* __restrict__ out, int n) {
    int idx = blockIdx.x * blockDim.x + threadIdx.x;
    if (idx < n) out[idx] = 0.0f;
}

__global__ __launch_bounds__(THREADS)
void synapses_kernel(const float* __restrict__ in_spikes,  // [B, N_IN]
                     const float* __restrict__ mem,        // [B, N_OUT]
                     const float* __restrict__ rev,        // [B, N_IN]
                     const float* __restrict__ syn,        // [B, N_IN, N_OUT]
                     const float* __restrict__ weights,    // [N_IN, N_OUT]
                     float* __restrict__ out)              // [B, N_OUT]
{
    __shared__ float s_sp[BB][CHUNK];
    __shared__ float s_rv[BB][CHUNK];

    const int b0 = blockIdx.y * BB;
    const int i0 = blockIdx.x * CHUNK;
    const int t  = threadIdx.x;

    // Stage per-(batch,i) scalars for this chunk.
    if (t < BB * CHUNK) {
        const int bb = t / CHUNK;
        const int ii = t % CHUNK;
        s_sp[bb][ii] = in_spikes[(b0 + bb) * N_IN + i0 + ii];
        s_rv[bb][ii] = rev[(b0 + bb) * N_IN + i0 + ii];
    }
    __syncthreads();

    const float decay = 1.0f - 1.0f / 5.0f;  // TAU = 5

    const float4* __restrict__ w4 =
        (const float4*)(weights + (size_t)i0 * N_OUT);
    const float4* __restrict__ sa =
        (const float4*)(syn + ((size_t)(b0 + 0) * N_IN + i0) * N_OUT);
    const float4* __restrict__ sbp =
        (const float4*)(syn + ((size_t)(b0 + 1) * N_IN + i0) * N_OUT);

    float4 ar0 = make_float4(0.f,0.f,0.f,0.f), as0 = make_float4(0.f,0.f,0.f,0.f);
    float4 ar1 = make_float4(0.f,0.f,0.f,0.f), as1 = make_float4(0.f,0.f,0.f,0.f);

    // 2 i-rows/iter; each W float4 serves 2 batches.
    // 6 float4 loads front-batched -> MLP_eff ~6, ~60 regs -> 4 CTAs/SM,
    // 512 CTAs < 592 capacity -> single wave (the R6 lesson).
    for (int i = 0; i < CHUNK; i += 2) {
        const float4 w0 = __ldg(w4 + (i + 0) * STRIDE + t);
        const float4 w1 = __ldg(w4 + (i + 1) * STRIDE + t);
        const float4 a0 = __ldcs(sa  + (i + 0) * STRIDE + t);  // streaming
        const float4 a1 = __ldcs(sa  + (i + 1) * STRIDE + t);
        const float4 b0v = __ldcs(sbp + (i + 0) * STRIDE + t);
        const float4 b1v = __ldcs(sbp + (i + 1) * STRIDE + t);

        {   // batch 0, row i
            const float sp = s_sp[0][i + 0], rv = s_rv[0][i + 0];
            float c0 = fmaf(a0.x, decay, sp) * w0.x;
            float c1 = fmaf(a0.y, decay, sp) * w0.y;
            float c2 = fmaf(a0.z, decay, sp) * w0.z;
            float c3 = fmaf(a0.w, decay, sp) * w0.w;
            ar0.x = fmaf(c0, rv, ar0.x);  as0.x += c0;
            ar0.y = fmaf(c1, rv, ar0.y);  as0.y += c1;
            ar0.z = fmaf(c2, rv, ar0.z);  as0.z += c2;
            ar0.w = fmaf(c3, rv, ar0.w);  as0.w += c3;
        }
        {   // batch 0, row i+1
            const float sp = s_sp[0][i + 1], rv = s_rv[0][i + 1];
            float c0 = fmaf(a1.x, decay, sp) * w1.x;
            float c1 = fmaf(a1.y, decay, sp) * w1.y;
            float c2 = fmaf(a1.z, decay, sp) * w1.z;
            float c3 = fmaf(a1.w, decay, sp) * w1.w;
            ar0.x = fmaf(c0, rv, ar0.x);  as0.x += c0;
            ar0.y = fmaf(c1, rv, ar0.y);  as0.y += c1;
            ar0.z = fmaf(c2, rv, ar0.z);  as0.z += c2;
            ar0.w = fmaf(c3, rv, ar0.w);  as0.w += c3;
        }
        {   // batch 1, row i
            const float sp = s_sp[1][i + 0], rv = s_rv[1][i + 0];
            float c0 = fmaf(b0v.x, decay, sp) * w0.x;
            float c1 = fmaf(b0v.y, decay, sp) * w0.y;
            float c2 = fmaf(b0v.z, decay, sp) * w0.z;
            float c3 = fmaf(b0v.w, decay, sp) * w0.w;
            ar1.x = fmaf(c0, rv, ar1.x);  as1.x += c0;
            ar1.y = fmaf(c1, rv, ar1.y);  as1.y += c1;
            ar1.z = fmaf(c2, rv, ar1.z);  as1.z += c2;
            ar1.w = fmaf(c3, rv, ar1.w);  as1.w += c3;
        }
        {   // batch 1, row i+1
            const float sp = s_sp[1][i + 1], rv = s_rv[1][i + 1];
            float c0 = fmaf(b1v.x, decay, sp) * w1.x;
            float c1 = fmaf(b1v.y, decay, sp) * w1.y;
            float c2 = fmaf(b1v.z, decay, sp) * w1.z;
            float c3 = fmaf(b1v.w, decay, sp) * w1.w;
            ar1.x = fmaf(c0, rv, ar1.x);  as1.x += c0;
            ar1.y = fmaf(c1, rv, ar1.y);  as1.y += c1;
            ar1.z = fmaf(c2, rv, ar1.z);  as1.z += c2;
            ar1.w = fmaf(c3, rv, ar1.w);  as1.w += c3;
        }
    }

    // Partial contribution of this i-chunk (linear in the i-partition).
    const int o = t * 4;
    {
        const float4 m = *(const float4*)(mem + (size_t)(b0 + 0) * N_OUT + o);
        float* dst = out + (size_t)(b0 + 0) * N_OUT + o;
        atomicAdd(dst + 0, fmaf(-m.x, as0.x, ar0.x));
        atomicAdd(dst + 1, fmaf(-m.y, as0.y, ar0.y));
        atomicAdd(dst + 2, fmaf(-m.z, as0.z, ar0.z));
        atomicAdd(dst + 3, fmaf(-m.w, as0.w, ar0.w));
    }
    {
        const float4 m = *(const float4*)(mem + (size_t)(b0 + 1) * N_OUT + o);
        float* dst = out + (size_t)(b0 + 1) * N_OUT + o;
        atomicAdd(dst + 0, fmaf(-m.x, as1.x, ar1.x));
        atomicAdd(dst + 1, fmaf(-m.y, as1.y, ar1.y));
        atomicAdd(dst + 2, fmaf(-m.z, as1.z, ar1.z));
        atomicAdd(dst + 3, fmaf(-m.w, as1.w, ar1.w));
    }
}

extern "C" void kernel_launch(void* const* d_in, const int* in_sizes, int n_in,
                              void* d_out, int out_size) {
    const float* in_spikes = (const float*)d_in[0];
    const float* mem       = (const float*)d_in[1];
    const float* rev       = (const float*)d_in[2];
    const float* syn       = (const float*)d_in[3];
    const float* weights   = (const float*)d_in[4];
    float* out = (float*)d_out;

    zero_out_kernel<<<(B_SZ * N_OUT + 255) / 256, 256>>>(out, B_SZ * N_OUT);

    dim3 grid(NCHUNK, NB);  // 32 x 16 = 512 CTAs
    synapses_kernel<<<grid, THREADS>>>(in_spikes, mem, rev, syn, weights, out);
}